// round 4
// baseline (speedup 1.0000x reference)
#include <cuda_runtime.h>
#include <cuda_bf16.h>
#include <mma.h>
#include <cstdint>

using namespace nvcuda;

#define B_SZ 16
#define N_SZ 2048
#define HID  128

// fp32 scratch (no allocation allowed -> __device__ globals)
__device__ float g_p[B_SZ * N_SZ * HID];   // 16 MB: projected features h @ W
__device__ float g_h[B_SZ * N_SZ * HID];   // 16 MB: layer output

// shared-memory strides (in floats)
#define SA_LD 36     // agg A tile: 128 x 32, pad to 36 (144B rows, 16B aligned)
#define SB_LD 132    // B/C tiles: 128-wide, pad to 132 (528B rows, 16B aligned)
#define SC_LD 132

#define STAGES 3
#define KC     32
#define A_STG  (128 * SA_LD)           // floats per A stage  (4608)
#define B_STG  (KC * SB_LD)            // floats per B stage  (4224)
#define B_BASE (STAGES * A_STG)        // 13824
#define STAT_BASE (B_BASE + STAGES * B_STG)   // 26496
#define AGG_SMEM ((STAT_BASE + 256) * 4)      // 107008 B
#define PW_SMEM  (2 * 128 * 132 * 4)          // 135168 B

// ---------------------------------------------------------------------------
__device__ __forceinline__ void cp_async16(float* smem, const float* gmem) {
    unsigned s = (unsigned)__cvta_generic_to_shared(smem);
    asm volatile("cp.async.cg.shared.global [%0], [%1], 16;\n" :: "r"(s), "l"(gmem));
}
__device__ __forceinline__ void cp_commit() {
    asm volatile("cp.async.commit_group;\n");
}
template<int N> __device__ __forceinline__ void cp_wait() {
    asm volatile("cp.async.wait_group %0;\n" :: "n"(N));
}

// ---------------------------------------------------------------------------
// pw_kernel: out[r, :] = src[r, :] @ W   (rows flattened over B*N, K=N=128)
// ---------------------------------------------------------------------------
__global__ __launch_bounds__(256) void pw_kernel(const float* __restrict__ src,
                                                 const float* __restrict__ W,
                                                 float* __restrict__ out)
{
    extern __shared__ float sm[];
    float* sA = sm;                    // 128 x 132
    float* sB = sm + 128 * 132;        // 128 x 132
    float* sC = sm;                    // overlays sA after compute

    const int tid  = threadIdx.x;
    const int warp = tid >> 5;
    const int wr   = warp >> 1;
    const int wc   = warp & 1;
    const size_t row0 = (size_t)blockIdx.x * 128;

    #pragma unroll
    for (int i = tid; i < 128 * 32; i += 256) {
        int r = i >> 5, c4 = i & 31;
        cp_async16(sA + r * SB_LD + c4 * 4, src + (row0 + r) * HID + c4 * 4);
    }
    #pragma unroll
    for (int i = tid; i < 128 * 32; i += 256) {
        int r = i >> 5, c4 = i & 31;
        cp_async16(sB + r * SB_LD + c4 * 4, W + r * HID + c4 * 4);
    }
    cp_commit();
    cp_wait<0>();
    __syncthreads();

    wmma::fragment<wmma::accumulator, 16, 16, 8, float> acc[2][4];
    #pragma unroll
    for (int i = 0; i < 2; i++)
        #pragma unroll
        for (int j = 0; j < 4; j++) wmma::fill_fragment(acc[i][j], 0.f);

    #pragma unroll
    for (int ks = 0; ks < 16; ++ks) {
        wmma::fragment<wmma::matrix_a, 16, 16, 8, wmma::precision::tf32, wmma::row_major> fa[2];
        wmma::fragment<wmma::matrix_b, 16, 16, 8, wmma::precision::tf32, wmma::row_major> fb[4];
        #pragma unroll
        for (int i = 0; i < 2; i++) {
            wmma::load_matrix_sync(fa[i], sA + (wr * 32 + i * 16) * SB_LD + ks * 8, SB_LD);
            #pragma unroll
            for (int t = 0; t < fa[i].num_elements; t++)
                fa[i].x[t] = wmma::__float_to_tf32(fa[i].x[t]);
        }
        #pragma unroll
        for (int j = 0; j < 4; j++) {
            wmma::load_matrix_sync(fb[j], sB + (ks * 8) * SB_LD + wc * 64 + j * 16, SB_LD);
            #pragma unroll
            for (int t = 0; t < fb[j].num_elements; t++)
                fb[j].x[t] = wmma::__float_to_tf32(fb[j].x[t]);
        }
        #pragma unroll
        for (int i = 0; i < 2; i++)
            #pragma unroll
            for (int j = 0; j < 4; j++)
                wmma::mma_sync(acc[i][j], fa[i], fb[j], acc[i][j]);
    }
    __syncthreads();

    #pragma unroll
    for (int i = 0; i < 2; i++)
        #pragma unroll
        for (int j = 0; j < 4; j++)
            wmma::store_matrix_sync(sC + (wr * 32 + i * 16) * SC_LD + wc * 64 + j * 16,
                                    acc[i][j], SC_LD, wmma::mem_row_major);
    __syncthreads();

    #pragma unroll
    for (int i = tid; i < 128 * 32; i += 256) {
        int r = i >> 5, c4 = i & 31;
        float4 v = *(const float4*)(sC + r * SC_LD + c4 * 4);
        *(float4*)(out + (row0 + r) * HID + c4 * 4) = v;
    }
}

// ---------------------------------------------------------------------------
// agg_kernel: C[128x128] = adj[b, n0:n0+128, :] @ p[b, :, :]; fused epilogue
// (+bias, LayerNorm over 128 cols, *gamma+beta, ReLU).
// 3-stage cp.async pipeline, KC=32.
// ---------------------------------------------------------------------------
__device__ __forceinline__ void agg_load_stage(float* sm, int stg,
                                               const float* __restrict__ adjb,
                                               const float* __restrict__ pb,
                                               int n0, int k0, int tid)
{
    float* sA = sm + stg * A_STG;
    float* sB = sm + B_BASE + stg * B_STG;
    #pragma unroll
    for (int it = 0; it < 4; ++it) {
        int i = tid + it * 256;
        int r = i >> 3, c4 = i & 7;
        cp_async16(sA + r * SA_LD + c4 * 4,
                   adjb + (size_t)(n0 + r) * N_SZ + k0 + c4 * 4);
    }
    #pragma unroll
    for (int it = 0; it < 4; ++it) {
        int i = tid + it * 256;
        int r = i >> 5, s = i & 31;
        cp_async16(sB + r * SB_LD + s * 4,
                   pb + (size_t)(k0 + r) * HID + s * 4);
    }
    cp_commit();
}

__global__ __launch_bounds__(256, 2) void agg_kernel(const float* __restrict__ adj,
                                                     const float* __restrict__ p,
                                                     const float* __restrict__ bias,
                                                     const float* __restrict__ gamma,
                                                     const float* __restrict__ beta,
                                                     float* __restrict__ out)
{
    extern __shared__ float sm[];
    float* sC  = sm;                   // 128 x 132 (overlays stage buffers at end)
    float* sMu = sm + STAT_BASE;       // 128
    float* sRs = sMu + 128;            // 128

    const int tid  = threadIdx.x;
    const int warp = tid >> 5;
    const int wr   = warp >> 1;
    const int wc   = warp & 1;
    const int b    = blockIdx.y;
    const int n0   = blockIdx.x * 128;

    const float* adjb = adj + (size_t)b * N_SZ * N_SZ;
    const float* pb   = p   + (size_t)b * N_SZ * HID;

    wmma::fragment<wmma::accumulator, 16, 16, 8, float> acc[2][4];
    #pragma unroll
    for (int i = 0; i < 2; i++)
        #pragma unroll
        for (int j = 0; j < 4; j++) wmma::fill_fragment(acc[i][j], 0.f);

    // prologue: preload STAGES-1 stages
    agg_load_stage(sm, 0, adjb, pb, n0, 0, tid);
    agg_load_stage(sm, 1, adjb, pb, n0, KC, tid);

    const int NT = N_SZ / KC;   // 64
    for (int kt = 0; kt < NT; ++kt) {
        cp_wait<STAGES - 2>();
        __syncthreads();   // stage kt data visible

        int nk = kt + STAGES - 1;
        if (nk < NT)
            agg_load_stage(sm, nk % STAGES, adjb, pb, n0, nk * KC, tid);

        const int stg = kt % STAGES;
        float* sA = sm + stg * A_STG;
        float* sB = sm + B_BASE + stg * B_STG;

        #pragma unroll
        for (int ks = 0; ks < KC / 8; ++ks) {
            wmma::fragment<wmma::matrix_a, 16, 16, 8, wmma::precision::tf32, wmma::row_major> fa[2];
            wmma::fragment<wmma::matrix_b, 16, 16, 8, wmma::precision::tf32, wmma::row_major> fb[4];
            #pragma unroll
            for (int i = 0; i < 2; i++) {
                wmma::load_matrix_sync(fa[i], sA + (wr * 32 + i * 16) * SA_LD + ks * 8, SA_LD);
                #pragma unroll
                for (int t = 0; t < fa[i].num_elements; t++)
                    fa[i].x[t] = wmma::__float_to_tf32(fa[i].x[t]);
            }
            #pragma unroll
            for (int j = 0; j < 4; j++) {
                wmma::load_matrix_sync(fb[j], sB + (ks * 8) * SB_LD + wc * 64 + j * 16, SB_LD);
                #pragma unroll
                for (int t = 0; t < fb[j].num_elements; t++)
                    fb[j].x[t] = wmma::__float_to_tf32(fb[j].x[t]);
            }
            #pragma unroll
            for (int i = 0; i < 2; i++)
                #pragma unroll
                for (int j = 0; j < 4; j++)
                    wmma::mma_sync(acc[i][j], fa[i], fb[j], acc[i][j]);
        }
    }
    __syncthreads();   // all compute done before overlaying stage smem with C

    #pragma unroll
    for (int i = 0; i < 2; i++)
        #pragma unroll
        for (int j = 0; j < 4; j++)
            wmma::store_matrix_sync(sC + (wr * 32 + i * 16) * SC_LD + wc * 64 + j * 16,
                                    acc[i][j], SC_LD, wmma::mem_row_major);
    __syncthreads();

    // per-row LayerNorm stats: 2 threads per row (64 cols each), shfl combine
    {
        int r = tid >> 1, half = tid & 1;
        const float* rp = sC + r * SC_LD + half * 64;
        const float* bp = bias + half * 64;
        float s = 0.f, s2 = 0.f;
        #pragma unroll 8
        for (int c = 0; c < 64; c++) {
            float v = rp[c] + __ldg(&bp[c]);
            s  += v;
            s2 += v * v;
        }
        s  += __shfl_xor_sync(0xFFFFFFFF, s, 1);
        s2 += __shfl_xor_sync(0xFFFFFFFF, s2, 1);
        if (half == 0) {
            float mu  = s * (1.f / 128.f);
            float var = s2 * (1.f / 128.f) - mu * mu;
            sMu[r] = mu;
            sRs[r] = rsqrtf(var + 1e-5f);
        }
    }
    __syncthreads();

    float* ob = out + ((size_t)b * N_SZ + n0) * HID;
    #pragma unroll
    for (int i = tid; i < 128 * 128; i += 256) {
        int r = i >> 7, c = i & 127;
        float v = sC[r * SC_LD + c] + __ldg(&bias[c]);
        v = (v - sMu[r]) * sRs[r] * __ldg(&gamma[c]) + __ldg(&beta[c]);
        ob[(size_t)r * HID + c] = fmaxf(v, 0.f);
    }
}

// ---------------------------------------------------------------------------
extern "C" void kernel_launch(void* const* d_in, const int* in_sizes, int n_in,
                              void* d_out, int out_size)
{
    const float* x   = (const float*)d_in[0];
    const float* adj = (const float*)d_in[1];
    const float* W[3]  = {(const float*)d_in[2],  (const float*)d_in[6],  (const float*)d_in[10]};
    const float* bb[3] = {(const float*)d_in[3],  (const float*)d_in[7],  (const float*)d_in[11]};
    const float* gg[3] = {(const float*)d_in[4],  (const float*)d_in[8],  (const float*)d_in[12]};
    const float* be[3] = {(const float*)d_in[5],  (const float*)d_in[9],  (const float*)d_in[13]};
    float* out = (float*)d_out;

    cudaFuncSetAttribute(pw_kernel,  cudaFuncAttributeMaxDynamicSharedMemorySize, PW_SMEM);
    cudaFuncSetAttribute(agg_kernel, cudaFuncAttributeMaxDynamicSharedMemorySize, AGG_SMEM);

    float *pp, *ph;
    cudaGetSymbolAddress((void**)&pp, g_p);
    cudaGetSymbolAddress((void**)&ph, g_h);

    dim3 aggGrid(N_SZ / 128, B_SZ);   // (16, 16)
    const float* h = x;
    for (int l = 0; l < 3; ++l) {
        pw_kernel<<<(B_SZ * N_SZ) / 128, 256, PW_SMEM>>>(h, W[l], pp);
        float* dst = (l == 2) ? out : ph;
        agg_kernel<<<aggGrid, 256, AGG_SMEM>>>(adj, pp, bb[l], gg[l], be[l], dst);
        h = ph;
    }
}

// round 6
// speedup vs baseline: 2.8911x; 2.8911x over previous
#include <cuda_runtime.h>
#include <cuda_fp16.h>
#include <mma.h>
#include <cstdint>

using namespace nvcuda;

#define B_SZ 16
#define N_SZ 2048
#define HID  128

// static scratch (no allocation allowed)
__device__ __half g_adjh[(size_t)B_SZ * N_SZ * N_SZ];   // 128 MB fp16 adjacency
__device__ __half g_p[(size_t)B_SZ * N_SZ * HID];       //   8 MB fp16 projected feats
__device__ float  g_h[(size_t)B_SZ * N_SZ * HID];       //  16 MB fp32 layer output

// ---------------------------------------------------------------------------
__device__ __forceinline__ void cp_async16(void* smem, const void* gmem) {
    unsigned s = (unsigned)__cvta_generic_to_shared(smem);
    asm volatile("cp.async.cg.shared.global [%0], [%1], 16;\n" :: "r"(s), "l"(gmem));
}
__device__ __forceinline__ void cp_commit() {
    asm volatile("cp.async.commit_group;\n");
}
template<int N> __device__ __forceinline__ void cp_wait() {
    asm volatile("cp.async.wait_group %0;\n" :: "n"(N));
}

// ---------------------------------------------------------------------------
// conv_adj: fp32 adjacency -> fp16 (once per launch, reused by 3 layers)
// ---------------------------------------------------------------------------
__global__ __launch_bounds__(256) void conv_adj(const float4* __restrict__ in,
                                                __half2* __restrict__ out,
                                                int n4)
{
    int i = blockIdx.x * blockDim.x + threadIdx.x;
    int stride = gridDim.x * blockDim.x;
    for (; i < n4; i += stride) {
        float4 v = in[i];
        out[2 * i + 0] = __floats2half2_rn(v.x, v.y);
        out[2 * i + 1] = __floats2half2_rn(v.z, v.w);
    }
}

// ---------------------------------------------------------------------------
// pw_kernel: p[b*n, :] = fp16_rn( src[b*n, :] @ W )   (tf32 wmma, K=128)
// ---------------------------------------------------------------------------
#define SC_LD 132
#define PW_SMEM (2 * 128 * 132 * 4)

__global__ __launch_bounds__(256) void pw_kernel(const float* __restrict__ src,
                                                 const float* __restrict__ W,
                                                 __half* __restrict__ out)
{
    extern __shared__ float sm[];
    float* sA = sm;                    // 128 x 132
    float* sB = sm + 128 * 132;        // 128 x 132
    float* sC = sm;                    // overlays sA after compute

    const int tid  = threadIdx.x;
    const int warp = tid >> 5;
    const int wr   = warp >> 1;
    const int wc   = warp & 1;
    const size_t row0 = (size_t)blockIdx.x * 128;

    #pragma unroll
    for (int i = tid; i < 128 * 32; i += 256) {
        int r = i >> 5, c4 = i & 31;
        cp_async16(sA + r * 132 + c4 * 4, src + (row0 + r) * HID + c4 * 4);
    }
    #pragma unroll
    for (int i = tid; i < 128 * 32; i += 256) {
        int r = i >> 5, c4 = i & 31;
        cp_async16(sB + r * 132 + c4 * 4, W + r * HID + c4 * 4);
    }
    cp_commit();
    cp_wait<0>();
    __syncthreads();

    wmma::fragment<wmma::accumulator, 16, 16, 8, float> acc[2][4];
    #pragma unroll
    for (int i = 0; i < 2; i++)
        #pragma unroll
        for (int j = 0; j < 4; j++) wmma::fill_fragment(acc[i][j], 0.f);

    #pragma unroll
    for (int ks = 0; ks < 16; ++ks) {
        wmma::fragment<wmma::matrix_a, 16, 16, 8, wmma::precision::tf32, wmma::row_major> fa[2];
        wmma::fragment<wmma::matrix_b, 16, 16, 8, wmma::precision::tf32, wmma::row_major> fb[4];
        #pragma unroll
        for (int i = 0; i < 2; i++) {
            wmma::load_matrix_sync(fa[i], sA + (wr * 32 + i * 16) * 132 + ks * 8, 132);
            #pragma unroll
            for (int t = 0; t < fa[i].num_elements; t++)
                fa[i].x[t] = wmma::__float_to_tf32(fa[i].x[t]);
        }
        #pragma unroll
        for (int j = 0; j < 4; j++) {
            wmma::load_matrix_sync(fb[j], sB + (ks * 8) * 132 + wc * 64 + j * 16, 132);
            #pragma unroll
            for (int t = 0; t < fb[j].num_elements; t++)
                fb[j].x[t] = wmma::__float_to_tf32(fb[j].x[t]);
        }
        #pragma unroll
        for (int i = 0; i < 2; i++)
            #pragma unroll
            for (int j = 0; j < 4; j++)
                wmma::mma_sync(acc[i][j], fa[i], fb[j], acc[i][j]);
    }
    __syncthreads();

    #pragma unroll
    for (int i = 0; i < 2; i++)
        #pragma unroll
        for (int j = 0; j < 4; j++)
            wmma::store_matrix_sync(sC + (wr * 32 + i * 16) * SC_LD + wc * 64 + j * 16,
                                    acc[i][j], SC_LD, wmma::mem_row_major);
    __syncthreads();

    __half* ob = out + row0 * HID;
    #pragma unroll
    for (int i = tid; i < 128 * 64; i += 256) {   // half2 granularity
        int r = i >> 6, c2 = i & 63;
        float2 v = *(const float2*)(sC + r * SC_LD + c2 * 2);
        *((__half2*)(ob + (size_t)r * HID) + c2) = __floats2half2_rn(v.x, v.y);
    }
}

// ---------------------------------------------------------------------------
// agg_half: C[128x128] = adjh[b, n0:+128, :] @ p[b, :, :]  (fp16 wmma m16n16k16,
// fp32 accum), fused +bias / LayerNorm / ReLU epilogue. 3-stage cp.async, KC=64.
// ---------------------------------------------------------------------------
#define KC     64
#define A_LDH  72                           // halfs per A row (64 + 8 pad)
#define B_LDH  136                          // halfs per B row (128 + 8 pad)
#define A_STGB (128 * A_LDH * 2)            // 18432 B
#define B_STGB (KC * B_LDH * 2)             // 17408 B
#define OFF_B  (3 * A_STGB)                 // 55296
#define OFF_ST (OFF_B + 3 * B_STGB)         // 107520
#define AGG_SMEM (OFF_ST + 1024)            // 108544 B

__device__ __forceinline__ void agg_load_stage(char* smem, int stg,
                                               const __half* __restrict__ adjb,
                                               const __half* __restrict__ pb,
                                               int k0, int tid)
{
    char* sA = smem + stg * A_STGB;
    char* sB = smem + OFF_B + stg * B_STGB;
    #pragma unroll
    for (int it = 0; it < 4; ++it) {        // 1024 chunks: 128 rows x 8
        int i = tid + it * 256;
        int r = i >> 3, c = i & 7;
        cp_async16(sA + (r * A_LDH + c * 8) * 2,
                   adjb + (size_t)r * N_SZ + k0 + c * 8);
    }
    #pragma unroll
    for (int it = 0; it < 4; ++it) {        // 1024 chunks: 64 rows x 16
        int i = tid + it * 256;
        int r = i >> 4, c = i & 15;
        cp_async16(sB + (r * B_LDH + c * 8) * 2,
                   pb + (size_t)(k0 + r) * HID + c * 8);
    }
    cp_commit();
}

__global__ __launch_bounds__(256, 2) void agg_half(const __half* __restrict__ adjh,
                                                   const __half* __restrict__ p,
                                                   const float* __restrict__ bias,
                                                   const float* __restrict__ gamma,
                                                   const float* __restrict__ beta,
                                                   float* __restrict__ out)
{
    extern __shared__ char smem[];
    float* sC  = (float*)smem;              // 128 x 132 fp32, overlays stages at end
    float* sMu = (float*)(smem + OFF_ST);   // 128
    float* sRs = sMu + 128;                 // 128

    const int tid  = threadIdx.x;
    const int warp = tid >> 5;
    const int wr   = warp >> 1;
    const int wc   = warp & 1;
    const int b    = blockIdx.y;
    const int n0   = blockIdx.x * 128;

    const __half* adjb = adjh + ((size_t)b * N_SZ + n0) * N_SZ;
    const __half* pb   = p + (size_t)b * N_SZ * HID;

    wmma::fragment<wmma::accumulator, 16, 16, 16, float> acc[2][4];
    #pragma unroll
    for (int i = 0; i < 2; i++)
        #pragma unroll
        for (int j = 0; j < 4; j++) wmma::fill_fragment(acc[i][j], 0.f);

    agg_load_stage(smem, 0, adjb, pb, 0, tid);
    agg_load_stage(smem, 1, adjb, pb, KC, tid);

    const int NT = N_SZ / KC;   // 32
    for (int kt = 0; kt < NT; ++kt) {
        cp_wait<1>();
        __syncthreads();

        int nk = kt + 2;
        if (nk < NT) {
            agg_load_stage(smem, nk % 3, adjb, pb, nk * KC, tid);
        } else {
            cp_commit();    // keep group counting uniform
        }

        const int stg = kt % 3;
        const __half* sA = (const __half*)(smem + stg * A_STGB);
        const __half* sB = (const __half*)(smem + OFF_B + stg * B_STGB);

        #pragma unroll
        for (int ks = 0; ks < KC / 16; ++ks) {
            wmma::fragment<wmma::matrix_a, 16, 16, 16, __half, wmma::row_major> fa[2];
            wmma::fragment<wmma::matrix_b, 16, 16, 16, __half, wmma::row_major> fb[4];
            #pragma unroll
            for (int i = 0; i < 2; i++)
                wmma::load_matrix_sync(fa[i], sA + (wr * 32 + i * 16) * A_LDH + ks * 16, A_LDH);
            #pragma unroll
            for (int j = 0; j < 4; j++)
                wmma::load_matrix_sync(fb[j], sB + (ks * 16) * B_LDH + wc * 64 + j * 16, B_LDH);
            #pragma unroll
            for (int i = 0; i < 2; i++)
                #pragma unroll
                for (int j = 0; j < 4; j++)
                    wmma::mma_sync(acc[i][j], fa[i], fb[j], acc[i][j]);
        }
    }
    __syncthreads();   // all compute done before overlaying stage smem with C

    #pragma unroll
    for (int i = 0; i < 2; i++)
        #pragma unroll
        for (int j = 0; j < 4; j++)
            wmma::store_matrix_sync(sC + (wr * 32 + i * 16) * SC_LD + wc * 64 + j * 16,
                                    acc[i][j], SC_LD, wmma::mem_row_major);
    __syncthreads();

    // per-row LayerNorm stats: 2 threads per row (64 cols each), shfl combine
    {
        int r = tid >> 1, half = tid & 1;
        const float* rp = sC + r * SC_LD + half * 64;
        const float* bp = bias + half * 64;
        float s = 0.f, s2 = 0.f;
        #pragma unroll 8
        for (int c = 0; c < 64; c++) {
            float v = rp[c] + __ldg(&bp[c]);
            s  += v;
            s2 += v * v;
        }
        s  += __shfl_xor_sync(0xFFFFFFFF, s, 1);
        s2 += __shfl_xor_sync(0xFFFFFFFF, s2, 1);
        if (half == 0) {
            float mu  = s * (1.f / 128.f);
            float var = s2 * (1.f / 128.f) - mu * mu;
            sMu[r] = mu;
            sRs[r] = rsqrtf(var + 1e-5f);
        }
    }
    __syncthreads();

    float* ob = out + ((size_t)b * N_SZ + n0) * HID;
    #pragma unroll
    for (int i = tid; i < 128 * 128; i += 256) {
        int r = i >> 7, c = i & 127;
        float v = sC[r * SC_LD + c] + __ldg(&bias[c]);
        v = (v - sMu[r]) * sRs[r] * __ldg(&gamma[c]) + __ldg(&beta[c]);
        ob[(size_t)r * HID + c] = fmaxf(v, 0.f);
    }
}

// ---------------------------------------------------------------------------
extern "C" void kernel_launch(void* const* d_in, const int* in_sizes, int n_in,
                              void* d_out, int out_size)
{
    const float* x   = (const float*)d_in[0];
    const float* adj = (const float*)d_in[1];
    const float* W[3]  = {(const float*)d_in[2],  (const float*)d_in[6],  (const float*)d_in[10]};
    const float* bb[3] = {(const float*)d_in[3],  (const float*)d_in[7],  (const float*)d_in[11]};
    const float* gg[3] = {(const float*)d_in[4],  (const float*)d_in[8],  (const float*)d_in[12]};
    const float* be[3] = {(const float*)d_in[5],  (const float*)d_in[9],  (const float*)d_in[13]};
    float* out = (float*)d_out;

    cudaFuncSetAttribute(pw_kernel, cudaFuncAttributeMaxDynamicSharedMemorySize, PW_SMEM);
    cudaFuncSetAttribute(agg_half,  cudaFuncAttributeMaxDynamicSharedMemorySize, AGG_SMEM);

    __half *adjh, *pp;
    float *ph;
    cudaGetSymbolAddress((void**)&adjh, g_adjh);
    cudaGetSymbolAddress((void**)&pp,   g_p);
    cudaGetSymbolAddress((void**)&ph,   g_h);

    // adjacency fp32 -> fp16 (once; reused by all 3 layers)
    int n4 = (B_SZ * N_SZ * N_SZ) / 4;
    conv_adj<<<4096, 256>>>((const float4*)adj, (__half2*)adjh, n4);

    dim3 aggGrid(N_SZ / 128, B_SZ);   // (16, 16)
    const float* h = x;
    for (int l = 0; l < 3; ++l) {
        pw_kernel<<<(B_SZ * N_SZ) / 128, 256, PW_SMEM>>>(h, W[l], pp);
        float* dst = (l == 2) ? out : ph;
        agg_half<<<aggGrid, 256, AGG_SMEM>>>(adjh, pp, bb[l], gg[l], be[l], dst);
        h = ph;
    }
}

// round 7
// speedup vs baseline: 3.3678x; 1.1649x over previous
#include <cuda_runtime.h>
#include <cuda_fp16.h>
#include <mma.h>
#include <cstdint>

using namespace nvcuda;

#define B_SZ 16
#define N_SZ 2048
#define HID  128

// static scratch (no allocation allowed)
__device__ __half g_adjh[(size_t)B_SZ * N_SZ * N_SZ];   // 128 MB fp16 adjacency
__device__ __half g_xh[(size_t)B_SZ * N_SZ * HID];      //   8 MB fp16 x
__device__ __half g_p[(size_t)B_SZ * N_SZ * HID];       //   8 MB fp16 projected feats
__device__ __half g_hh[(size_t)B_SZ * N_SZ * HID];      //   8 MB fp16 intermediate h
__device__ __half g_wh[3 * HID * HID];                  //  96 KB fp16 weights

// ---------------------------------------------------------------------------
__device__ __forceinline__ void cp_async16(void* smem, const void* gmem) {
    unsigned s = (unsigned)__cvta_generic_to_shared(smem);
    asm volatile("cp.async.cg.shared.global [%0], [%1], 16;\n" :: "r"(s), "l"(gmem));
}
__device__ __forceinline__ void cp_commit() {
    asm volatile("cp.async.commit_group;\n");
}
template<int N> __device__ __forceinline__ void cp_wait() {
    asm volatile("cp.async.wait_group %0;\n" :: "n"(N));
}

// ---------------------------------------------------------------------------
// conv: fp32 -> fp16, vectorized (adjacency, x, weights)
// ---------------------------------------------------------------------------
__global__ __launch_bounds__(256) void conv_fp16(const float4* __restrict__ in,
                                                 __half2* __restrict__ out,
                                                 int n4)
{
    int i = blockIdx.x * blockDim.x + threadIdx.x;
    int stride = gridDim.x * blockDim.x;
    for (; i < n4; i += stride) {
        float4 v = in[i];
        out[2 * i + 0] = __floats2half2_rn(v.x, v.y);
        out[2 * i + 1] = __floats2half2_rn(v.z, v.w);
    }
}

// converts the three 128x128 weight matrices in one launch
__global__ __launch_bounds__(256) void conv_w(const float* __restrict__ W0,
                                              const float* __restrict__ W1,
                                              const float* __restrict__ W2,
                                              __half* __restrict__ out)
{
    int i = blockIdx.x * blockDim.x + threadIdx.x;           // 0 .. 3*16384-1
    const float* src = (i < 16384) ? W0 : (i < 32768) ? W1 : W2;
    int off = i & 16383;
    out[i] = __float2half_rn(src[off]);
}

// ---------------------------------------------------------------------------
// pw_half: p[r, :] = fp16( src[r, :] @ W )   fp16 wmma m16n16k16, K=128
// ---------------------------------------------------------------------------
#define PW_LD   136                         // halfs per smem row (128 + 8 pad)
#define SC_LD   132
#define PW_SMEM (2 * 128 * PW_LD * 2)       // 69632 B (sC fp32 overlays)

__global__ __launch_bounds__(256, 2) void pw_half(const __half* __restrict__ src,
                                                  const __half* __restrict__ W,
                                                  __half* __restrict__ out)
{
    extern __shared__ char smraw[];
    __half* sA = (__half*)smraw;                    // 128 x 136
    __half* sB = sA + 128 * PW_LD;                  // 128 x 136
    float*  sC = (float*)smraw;                     // 128 x 132 fp32 overlay

    const int tid  = threadIdx.x;
    const int warp = tid >> 5;
    const int wr   = warp >> 1;
    const int wc   = warp & 1;
    const size_t row0 = (size_t)blockIdx.x * 128;

    #pragma unroll
    for (int it = 0; it < 8; ++it) {                // 2048 16B-chunks for A
        int i = tid + it * 256;
        int r = i >> 4, c = i & 15;
        cp_async16(sA + r * PW_LD + c * 8, src + (row0 + r) * HID + c * 8);
    }
    #pragma unroll
    for (int it = 0; it < 8; ++it) {                // 2048 16B-chunks for B
        int i = tid + it * 256;
        int r = i >> 4, c = i & 15;
        cp_async16(sB + r * PW_LD + c * 8, W + r * HID + c * 8);
    }
    cp_commit();
    cp_wait<0>();
    __syncthreads();

    wmma::fragment<wmma::accumulator, 16, 16, 16, float> acc[2][4];
    #pragma unroll
    for (int i = 0; i < 2; i++)
        #pragma unroll
        for (int j = 0; j < 4; j++) wmma::fill_fragment(acc[i][j], 0.f);

    #pragma unroll
    for (int ks = 0; ks < 8; ++ks) {
        wmma::fragment<wmma::matrix_a, 16, 16, 16, __half, wmma::row_major> fa[2];
        wmma::fragment<wmma::matrix_b, 16, 16, 16, __half, wmma::row_major> fb[4];
        #pragma unroll
        for (int i = 0; i < 2; i++)
            wmma::load_matrix_sync(fa[i], sA + (wr * 32 + i * 16) * PW_LD + ks * 16, PW_LD);
        #pragma unroll
        for (int j = 0; j < 4; j++)
            wmma::load_matrix_sync(fb[j], sB + (ks * 16) * PW_LD + wc * 64 + j * 16, PW_LD);
        #pragma unroll
        for (int i = 0; i < 2; i++)
            #pragma unroll
            for (int j = 0; j < 4; j++)
                wmma::mma_sync(acc[i][j], fa[i], fb[j], acc[i][j]);
    }
    __syncthreads();

    #pragma unroll
    for (int i = 0; i < 2; i++)
        #pragma unroll
        for (int j = 0; j < 4; j++)
            wmma::store_matrix_sync(sC + (wr * 32 + i * 16) * SC_LD + wc * 64 + j * 16,
                                    acc[i][j], SC_LD, wmma::mem_row_major);
    __syncthreads();

    __half* ob = out + row0 * HID;
    #pragma unroll
    for (int i = tid; i < 128 * 64; i += 256) {     // half2 granularity
        int r = i >> 6, c2 = i & 63;
        float2 v = *(const float2*)(sC + r * SC_LD + c2 * 2);
        *((__half2*)(ob + (size_t)r * HID) + c2) = __floats2half2_rn(v.x, v.y);
    }
}

// ---------------------------------------------------------------------------
// agg_half: C[128x128] = adjh[b, n0:+128, :] @ p[b, :, :]  (fp16 wmma, fp32
// accum), fused +bias / LayerNorm / ReLU epilogue. 3-stage cp.async, KC=64.
// OutT = __half (intermediate layers) or float (final output).
// ---------------------------------------------------------------------------
#define KC     64
#define A_LDH  72                           // halfs per A row (64 + 8 pad)
#define B_LDH  136                          // halfs per B row (128 + 8 pad)
#define A_STGB (128 * A_LDH * 2)            // 18432 B
#define B_STGB (KC * B_LDH * 2)             // 17408 B
#define OFF_B  (3 * A_STGB)                 // 55296
#define OFF_ST (OFF_B + 3 * B_STGB)         // 107520
#define AGG_SMEM (OFF_ST + 1024)            // 108544 B

__device__ __forceinline__ void agg_load_stage(char* smem, int stg,
                                               const __half* __restrict__ adjb,
                                               const __half* __restrict__ pb,
                                               int k0, int tid)
{
    char* sA = smem + stg * A_STGB;
    char* sB = smem + OFF_B + stg * B_STGB;
    #pragma unroll
    for (int it = 0; it < 4; ++it) {        // 1024 chunks: 128 rows x 8
        int i = tid + it * 256;
        int r = i >> 3, c = i & 7;
        cp_async16(sA + (r * A_LDH + c * 8) * 2,
                   adjb + (size_t)r * N_SZ + k0 + c * 8);
    }
    #pragma unroll
    for (int it = 0; it < 4; ++it) {        // 1024 chunks: 64 rows x 16
        int i = tid + it * 256;
        int r = i >> 4, c = i & 15;
        cp_async16(sB + (r * B_LDH + c * 8) * 2,
                   pb + (size_t)(k0 + r) * HID + c * 8);
    }
    cp_commit();
}

template<typename OutT>
__global__ __launch_bounds__(256, 2) void agg_half(const __half* __restrict__ adjh,
                                                   const __half* __restrict__ p,
                                                   const float* __restrict__ bias,
                                                   const float* __restrict__ gamma,
                                                   const float* __restrict__ beta,
                                                   OutT* __restrict__ out)
{
    extern __shared__ char smem[];
    float* sC  = (float*)smem;              // 128 x 132 fp32, overlays stages at end
    float* sMu = (float*)(smem + OFF_ST);   // 128
    float* sRs = sMu + 128;                 // 128

    const int tid  = threadIdx.x;
    const int warp = tid >> 5;
    const int wr   = warp >> 1;
    const int wc   = warp & 1;
    const int b    = blockIdx.y;
    const int n0   = blockIdx.x * 128;

    const __half* adjb = adjh + ((size_t)b * N_SZ + n0) * N_SZ;
    const __half* pb   = p + (size_t)b * N_SZ * HID;

    wmma::fragment<wmma::accumulator, 16, 16, 16, float> acc[2][4];
    #pragma unroll
    for (int i = 0; i < 2; i++)
        #pragma unroll
        for (int j = 0; j < 4; j++) wmma::fill_fragment(acc[i][j], 0.f);

    agg_load_stage(smem, 0, adjb, pb, 0, tid);
    agg_load_stage(smem, 1, adjb, pb, KC, tid);

    const int NT = N_SZ / KC;   // 32
    for (int kt = 0; kt < NT; ++kt) {
        cp_wait<1>();
        __syncthreads();

        int nk = kt + 2;
        if (nk < NT) {
            agg_load_stage(smem, nk % 3, adjb, pb, nk * KC, tid);
        } else {
            cp_commit();    // keep group counting uniform
        }

        const int stg = kt % 3;
        const __half* sA = (const __half*)(smem + stg * A_STGB);
        const __half* sB = (const __half*)(smem + OFF_B + stg * B_STGB);

        #pragma unroll
        for (int ks = 0; ks < KC / 16; ++ks) {
            wmma::fragment<wmma::matrix_a, 16, 16, 16, __half, wmma::row_major> fa[2];
            wmma::fragment<wmma::matrix_b, 16, 16, 16, __half, wmma::row_major> fb[4];
            #pragma unroll
            for (int i = 0; i < 2; i++)
                wmma::load_matrix_sync(fa[i], sA + (wr * 32 + i * 16) * A_LDH + ks * 16, A_LDH);
            #pragma unroll
            for (int j = 0; j < 4; j++)
                wmma::load_matrix_sync(fb[j], sB + (ks * 16) * B_LDH + wc * 64 + j * 16, B_LDH);
            #pragma unroll
            for (int i = 0; i < 2; i++)
                #pragma unroll
                for (int j = 0; j < 4; j++)
                    wmma::mma_sync(acc[i][j], fa[i], fb[j], acc[i][j]);
        }
    }
    __syncthreads();   // all compute done before overlaying stage smem with C

    #pragma unroll
    for (int i = 0; i < 2; i++)
        #pragma unroll
        for (int j = 0; j < 4; j++)
            wmma::store_matrix_sync(sC + (wr * 32 + i * 16) * SC_LD + wc * 64 + j * 16,
                                    acc[i][j], SC_LD, wmma::mem_row_major);
    __syncthreads();

    // per-row LayerNorm stats: 2 threads per row (64 cols each), shfl combine
    {
        int r = tid >> 1, half = tid & 1;
        const float* rp = sC + r * SC_LD + half * 64;
        const float* bp = bias + half * 64;
        float s = 0.f, s2 = 0.f;
        #pragma unroll 8
        for (int c = 0; c < 64; c++) {
            float v = rp[c] + __ldg(&bp[c]);
            s  += v;
            s2 += v * v;
        }
        s  += __shfl_xor_sync(0xFFFFFFFF, s, 1);
        s2 += __shfl_xor_sync(0xFFFFFFFF, s2, 1);
        if (half == 0) {
            float mu  = s * (1.f / 128.f);
            float var = s2 * (1.f / 128.f) - mu * mu;
            sMu[r] = mu;
            sRs[r] = rsqrtf(var + 1e-5f);
        }
    }
    __syncthreads();

    OutT* ob = out + ((size_t)b * N_SZ + n0) * HID;
    #pragma unroll
    for (int i = tid; i < 128 * 128; i += 256) {
        int r = i >> 7, c = i & 127;
        float v = sC[r * SC_LD + c] + __ldg(&bias[c]);
        v = (v - sMu[r]) * sRs[r] * __ldg(&gamma[c]) + __ldg(&beta[c]);
        v = fmaxf(v, 0.f);
        if constexpr (sizeof(OutT) == 2)
            ob[(size_t)r * HID + c] = __float2half_rn(v);
        else
            ob[(size_t)r * HID + c] = v;
    }
}

// ---------------------------------------------------------------------------
extern "C" void kernel_launch(void* const* d_in, const int* in_sizes, int n_in,
                              void* d_out, int out_size)
{
    const float* x   = (const float*)d_in[0];
    const float* adj = (const float*)d_in[1];
    const float* W[3]  = {(const float*)d_in[2],  (const float*)d_in[6],  (const float*)d_in[10]};
    const float* bb[3] = {(const float*)d_in[3],  (const float*)d_in[7],  (const float*)d_in[11]};
    const float* gg[3] = {(const float*)d_in[4],  (const float*)d_in[8],  (const float*)d_in[12]};
    const float* be[3] = {(const float*)d_in[5],  (const float*)d_in[9],  (const float*)d_in[13]};
    float* out = (float*)d_out;

    cudaFuncSetAttribute(pw_half, cudaFuncAttributeMaxDynamicSharedMemorySize, PW_SMEM);
    cudaFuncSetAttribute(agg_half<__half>, cudaFuncAttributeMaxDynamicSharedMemorySize, AGG_SMEM);
    cudaFuncSetAttribute(agg_half<float>,  cudaFuncAttributeMaxDynamicSharedMemorySize, AGG_SMEM);

    __half *adjh, *xh, *pp, *hh, *wh;
    cudaGetSymbolAddress((void**)&adjh, g_adjh);
    cudaGetSymbolAddress((void**)&xh,   g_xh);
    cudaGetSymbolAddress((void**)&pp,   g_p);
    cudaGetSymbolAddress((void**)&hh,   g_hh);
    cudaGetSymbolAddress((void**)&wh,   g_wh);

    // one-time fp32 -> fp16 conversions
    conv_fp16<<<4096, 256>>>((const float4*)adj, (__half2*)adjh, (B_SZ * N_SZ * N_SZ) / 4);
    conv_fp16<<<1024, 256>>>((const float4*)x,   (__half2*)xh,   (B_SZ * N_SZ * HID) / 4);
    conv_w<<<192, 256>>>(W[0], W[1], W[2], wh);

    dim3 aggGrid(N_SZ / 128, B_SZ);   // (16, 16)
    const __half* h = xh;
    for (int l = 0; l < 3; ++l) {
        pw_half<<<(B_SZ * N_SZ) / 128, 256, PW_SMEM>>>(h, wh + l * HID * HID, pp);
        if (l == 2)
            agg_half<float><<<aggGrid, 256, AGG_SMEM>>>(adjh, pp, bb[l], gg[l], be[l], out);
        else
            agg_half<__half><<<aggGrid, 256, AGG_SMEM>>>(adjh, pp, bb[l], gg[l], be[l], hh);
        h = hh;
    }
}